// round 11
// baseline (speedup 1.0000x reference)
#include <cuda_runtime.h>
#include <stdint.h>

#define D 128
#define K 16
#define TPB 128
#define WARPS 4
#define WROWS 32               // rows per warp unit; lane group p2 owns rows p2+8*rr
#define NSTEP 32               // 512B row / 16B per step
#define NBLK 888               // persistent: 148 SMs x 6 CTAs

// Precomputed A in (cp, k) pair-major: ull index cp*16+k holds f32x2 (A[k][2cp],A[k][2cp+1])
__device__ __align__(16) float gAp[(D / 2) * K * 2];
__device__ float gC[K];
__device__ unsigned int gCtr;   // work-stealing counter (reset by prep each launch)

// ---------------- helpers ----------------
__device__ __forceinline__ void ffma2(unsigned long long& c, unsigned long long a, unsigned long long b) {
    asm("fma.rn.f32x2 %0, %1, %2, %0;" : "+l"(c) : "l"(a), "l"(b));
}
__device__ __forceinline__ void unpack2(float& lo, float& hi, unsigned long long v) {
    asm("mov.b64 {%0, %1}, %2;" : "=f"(lo), "=f"(hi) : "l"(v));
}
__device__ __forceinline__ ulonglong2 lds128(uint32_t addr) {
    ulonglong2 q;
    asm volatile("ld.shared.v2.u64 {%0,%1}, [%2];" : "=l"(q.x), "=l"(q.y) : "r"(addr));
    return q;
}
__device__ __forceinline__ ulonglong2 ldg128(const void* p) {
    ulonglong2 q;
    asm volatile("ld.global.nc.v2.u64 {%0,%1}, [%2];" : "=l"(q.x), "=l"(q.y) : "l"(p));
    return q;
}

// ---------------- merged prep (single launch) ----------------
__global__ void ntn_prep(const float* __restrict__ x2,
                         const float* __restrict__ V,
                         const float* __restrict__ W,
                         const float* __restrict__ b) {
    const int lane = threadIdx.x & 31;
    const int wid = threadIdx.x >> 5;
    const float4 x4 = ((const float4*)x2)[lane];

    if (blockIdx.x < 128) {
        const int gw = blockIdx.x * 4 + wid;        // 0..511, rows 4gw..4gw+3
        float4 w4[4];
#pragma unroll
        for (int rr = 0; rr < 4; rr++)
            w4[rr] = ((const float4*)(W + (size_t)(gw * 4 + rr) * D))[lane];
        float dots[4];
#pragma unroll
        for (int rr = 0; rr < 4; rr++)
            dots[rr] = w4[rr].x * x4.x + w4[rr].y * x4.y + w4[rr].z * x4.z + w4[rr].w * x4.w;
#pragma unroll
        for (int s = 16; s > 0; s >>= 1) {
#pragma unroll
            for (int rr = 0; rr < 4; rr++)
                dots[rr] += __shfl_xor_sync(0xffffffffu, dots[rr], s);
        }
        if (lane == 0) {
#pragma unroll
            for (int rr = 0; rr < 4; rr++) {
                const int row = gw * 4 + rr;        // = k*128 + d
                const int k = row >> 7, d = row & (D - 1);
                gAp[((d >> 1) * K + k) * 2 + (d & 1)] = V[(size_t)k * 2 * D + d] + dots[rr];
            }
        }
    } else {
        if (threadIdx.x == 0) gCtr = 0u;            // reset work-stealing counter each launch
#pragma unroll
        for (int kk = 0; kk < 4; kk++) {
            const int k = wid * 4 + kk;
            const float4 v4 = ((const float4*)(V + (size_t)k * 2 * D + D))[lane];
            float dot = v4.x * x4.x + v4.y * x4.y + v4.z * x4.z + v4.w * x4.w;
#pragma unroll
            for (int s = 16; s > 0; s >>= 1)
                dot += __shfl_xor_sync(0xffffffffu, dot, s);
            if (lane == 0) gC[k] = dot + b[k];
        }
    }
}

// ---------------- main: no smem staging, register double-buffered LDG, work stealing ----------------
__global__ __launch_bounds__(TPB, 6)
void ntn_main(const float* __restrict__ x1,
              const float* __restrict__ U,
              float* __restrict__ out, int n, int nunits) {
    __shared__ __align__(16) unsigned long long sA[1024];   // A, cp-major (8 KB)
    __shared__ float sC[K], sU[K];

    const int tid = threadIdx.x;
    const int lane = tid & 31;
    const int h2 = lane & 3;         // k-quarter: owns k = h2*4 .. h2*4+3
    const int p2 = lane >> 2;        // row group: rows p2 + 8*rr, rr=0..3

    // header: A, c, U
    {
        const unsigned long long* gAu = (const unsigned long long*)gAp;
#pragma unroll
        for (int i = 0; i < 8; i++) sA[tid + i * TPB] = gAu[tid + i * TPB];
        if (tid < K) { sC[tid] = gC[tid]; sU[tid] = U[tid]; }
    }
    __syncthreads();

    const uint32_t sA_u32 = (uint32_t)__cvta_generic_to_shared(sA) + (uint32_t)(h2 * 32);

    // row0 for a unit (clamped so all 32 rows are in-bounds; duplicate rows recompute identically)
    auto unit_row0 = [&](unsigned int uu) -> int {
        int r0 = (int)uu * WROWS;
        if (r0 + WROWS > n) r0 = n - WROWS;
        return r0;
    };

    // grab first unit
    unsigned int u;
    if (lane == 0) u = atomicAdd(&gCtr, 1u);
    u = __shfl_sync(0xffffffffu, u, 0);

    // prefetch state: (pu, ps, pbase). pbase points at row (row0 + p2), stepping 16B per step.
    unsigned int pu = u;
    int ps = 0;
    const char* pbase = (const char*)x1;
    if (u < (unsigned)nunits)
        pbase = (const char*)(x1 + ((size_t)unit_row0(u) + p2) * D);

    ulonglong2 xb0[4], xb1[4];

    auto pf = [&](ulonglong2* dst) {
#pragma unroll
        for (int rr = 0; rr < 4; rr++)
            dst[rr] = ldg128(pbase + rr * (8 * D * 4) + ps * 16);
        if (++ps == NSTEP) {               // unit finished streaming: grab the next one
            ps = 0;
            unsigned int nu;
            if (lane == 0) nu = atomicAdd(&gCtr, 1u);
            nu = __shfl_sync(0xffffffffu, nu, 0);
            pu = nu;
            if (pu < (unsigned)nunits)
                pbase = (const char*)(x1 + ((size_t)unit_row0(pu) + p2) * D);
        }
    };

    if (u < (unsigned)nunits) { pf(xb0); pf(xb1); }   // steps 0,1 in flight

    while (u < (unsigned)nunits) {
        unsigned long long acc[4][4];
#pragma unroll
        for (int rr = 0; rr < 4; rr++)
#pragma unroll
            for (int j = 0; j < 4; j++) acc[rr][j] = 0ull;

        // step s covers col-pairs 2s, 2s+1 (16B = 4 cols of the row)
        auto step = [&](int s, const ulonglong2* xq) {
            const uint32_t ab = sA_u32 + (uint32_t)(s * 256);
#pragma unroll
            for (int e = 0; e < 2; e++) {
                const ulonglong2 a01 = lds128(ab + (uint32_t)(e * 128));       // k = h2*4, +1
                const ulonglong2 a23 = lds128(ab + (uint32_t)(e * 128 + 16));  // k = h2*4+2, +3
#pragma unroll
                for (int rr = 0; rr < 4; rr++) {
                    const unsigned long long xv = e ? xq[rr].y : xq[rr].x;
                    ffma2(acc[rr][0], xv, a01.x);
                    ffma2(acc[rr][1], xv, a01.y);
                    ffma2(acc[rr][2], xv, a23.x);
                    ffma2(acc[rr][3], xv, a23.y);
                }
            }
        };

#pragma unroll 4
        for (int s2 = 0; s2 < NSTEP; s2 += 2) {
            step(s2, xb0);      pf(xb0);      // loads s2+2 (wraps seamlessly into next unit)
            step(s2 + 1, xb1);  pf(xb1);
        }

        // epilogue: per-row partial over lane's 4 k, reduce across the 4-lane k-group
        const int row0 = unit_row0(u);
#pragma unroll
        for (int rr = 0; rr < 4; rr++) {
            float part = 0.f;
#pragma unroll
            for (int j = 0; j < 4; j++) {
                float lo, hi;
                unpack2(lo, hi, acc[rr][j]);
                const int k = h2 * 4 + j;
                const float s = lo + hi + sC[k];
                part = fmaf(fmaxf(s, 0.f), sU[k], part);
            }
            part += __shfl_xor_sync(0xffffffffu, part, 1);
            part += __shfl_xor_sync(0xffffffffu, part, 2);
            const int row = row0 + rr * 8 + p2;
            if (h2 == 0) out[row] = part;
        }

        u = pu;   // the unit whose steps 0,1 are already in xb0/xb1
    }
}

// ---------------- launch ----------------
extern "C" void kernel_launch(void* const* d_in, const int* in_sizes, int n_in,
                              void* d_out, int out_size) {
    const float* x1 = nullptr; const float* x2 = nullptr; const float* V = nullptr;
    const float* W = nullptr;  const float* b = nullptr;  const float* U = nullptr;
    int n16 = 0;
    for (int i = 0; i < n_in; i++) {
        const int s = in_sizes[i];
        const float* p = (const float*)d_in[i];
        if (s == 128) x2 = p;
        else if (s == 4096) V = p;
        else if (s == 262144) W = p;
        else if (s == 16) { if (n16++ == 0) b = p; else U = p; }
        else x1 = p;
    }
    int n = 0;
    for (int i = 0; i < n_in; i++) if ((const float*)d_in[i] == x1) n = in_sizes[i] / D;

    float* out = (float*)d_out;

    ntn_prep<<<129, TPB>>>(x2, V, W, b);

    const int nunits = (n + WROWS - 1) / WROWS;
    int blocks = (nunits * 8 + WARPS - 1) / WARPS;   // cap below
    if (blocks > NBLK) blocks = NBLK;
    ntn_main<<<blocks, TPB>>>(x1, U, out, n, nunits);
}

// round 12
// speedup vs baseline: 2.0280x; 2.0280x over previous
#include <cuda_runtime.h>
#include <stdint.h>

#define D 128
#define K 16
#define TPB 128
#define WARPS 4
#define WROWS 32                // rows per warp unit; lane group p2 owns rows p2+8*rr
#define CH 16                   // columns per chunk
#define NCH 8                   // chunks per unit (D/CH)
#define ROWSTRIDE 80            // 64B data + 16B pad: conflict-free LDS.128, 16B aligned
#define STAGE_BYTES (WROWS * ROWSTRIDE)      // 2560
#define WARP_STAGING (2 * STAGE_BYTES)       // 2 stages = 5120
#define SMEM_HDR 8448           // A (8192) + c/U + pad
#define SMEM_TOTAL (SMEM_HDR + WARPS * WARP_STAGING)  // 28928 -> 6 CTAs/SM
#define NBLK 888                // persistent: 148 SMs x 6 CTAs

// Precomputed A in (cp, k) pair-major: ull index cp*16+k holds f32x2 (A[k][2cp],A[k][2cp+1])
__device__ __align__(16) float gAp[(D / 2) * K * 2];
__device__ float gC[K];

// ---------------- helpers ----------------
__device__ __forceinline__ void ffma2(unsigned long long& c, unsigned long long a, unsigned long long b) {
    asm("fma.rn.f32x2 %0, %1, %2, %0;" : "+l"(c) : "l"(a), "l"(b));
}
__device__ __forceinline__ void unpack2(float& lo, float& hi, unsigned long long v) {
    asm("mov.b64 {%0, %1}, %2;" : "=f"(lo), "=f"(hi) : "l"(v));
}
__device__ __forceinline__ void cp_async16(uint32_t dst, const void* src, int src_bytes) {
    asm volatile("cp.async.cg.shared.global [%0], [%1], 16, %2;\n"
                 :: "r"(dst), "l"(src), "r"(src_bytes));
}
__device__ __forceinline__ void cp_commit() {
    asm volatile("cp.async.commit_group;\n" ::: "memory");
}
__device__ __forceinline__ void cp_wait1() {
    asm volatile("cp.async.wait_group 1;\n" ::: "memory");
}
__device__ __forceinline__ ulonglong2 lds128(uint32_t addr) {
    ulonglong2 q;
    asm volatile("ld.shared.v2.u64 {%0,%1}, [%2];" : "=l"(q.x), "=l"(q.y) : "r"(addr));
    return q;
}

// ---------------- merged prep (single launch) ----------------
__global__ void ntn_prep(const float* __restrict__ x2,
                         const float* __restrict__ V,
                         const float* __restrict__ W,
                         const float* __restrict__ b) {
    const int lane = threadIdx.x & 31;
    const int wid = threadIdx.x >> 5;
    const float4 x4 = ((const float4*)x2)[lane];

    if (blockIdx.x < 128) {
        const int gw = blockIdx.x * 4 + wid;        // 0..511, rows 4gw..4gw+3
        float4 w4[4];
#pragma unroll
        for (int rr = 0; rr < 4; rr++)
            w4[rr] = ((const float4*)(W + (size_t)(gw * 4 + rr) * D))[lane];
        float dots[4];
#pragma unroll
        for (int rr = 0; rr < 4; rr++)
            dots[rr] = w4[rr].x * x4.x + w4[rr].y * x4.y + w4[rr].z * x4.z + w4[rr].w * x4.w;
#pragma unroll
        for (int s = 16; s > 0; s >>= 1) {
#pragma unroll
            for (int rr = 0; rr < 4; rr++)
                dots[rr] += __shfl_xor_sync(0xffffffffu, dots[rr], s);
        }
        if (lane == 0) {
#pragma unroll
            for (int rr = 0; rr < 4; rr++) {
                const int row = gw * 4 + rr;        // = k*128 + d
                const int k = row >> 7, d = row & (D - 1);
                gAp[((d >> 1) * K + k) * 2 + (d & 1)] = V[(size_t)k * 2 * D + d] + dots[rr];
            }
        }
    } else {
#pragma unroll
        for (int kk = 0; kk < 4; kk++) {
            const int k = wid * 4 + kk;
            const float4 v4 = ((const float4*)(V + (size_t)k * 2 * D + D))[lane];
            float dot = v4.x * x4.x + v4.y * x4.y + v4.z * x4.z + v4.w * x4.w;
#pragma unroll
            for (int s = 16; s > 0; s >>= 1)
                dot += __shfl_xor_sync(0xffffffffu, dot, s);
            if (lane == 0) gC[k] = dot + b[k];
        }
    }
}

// ---------------- main: persistent per-warp units, k-quarter x 4-row fragments, 2-stage static parity ----------------
__global__ __launch_bounds__(TPB, 6)
void ntn_main(const float* __restrict__ x1,
              const float* __restrict__ U,
              float* __restrict__ out, int n, int nunits, int nw) {
    extern __shared__ __align__(16) char smem_raw[];
    unsigned long long* sA = (unsigned long long*)smem_raw;   // 1024 ull, cp-major
    float* sC = (float*)(smem_raw + 8192);
    float* sU = sC + K;

    const int tid = threadIdx.x;
    const int wid = tid >> 5;
    const int lane = tid & 31;
    const int h2 = lane & 3;         // k-quarter: owns k = h2*4 .. h2*4+3
    const int p2 = lane >> 2;        // row group: rows p2 + 8*rr, rr=0..3

    const uint32_t smem_u32 = (uint32_t)__cvta_generic_to_shared(smem_raw);
    const uint32_t sA_u32 = smem_u32 + (uint32_t)(h2 * 32);
    const uint32_t wstage_u32 = smem_u32 + SMEM_HDR + (uint32_t)wid * WARP_STAGING;
    const uint32_t xoff = (uint32_t)p2 * ROWSTRIDE;   // row rr at + rr*8*ROWSTRIDE

    // per-warp chunk issue: 32 rows x 16 cols (64B/row) -> 4 cp.async16 per lane
    auto issue = [&](int unit, int ch, int buf) {
        const uint32_t base = wstage_u32 + (uint32_t)buf * STAGE_BYTES;
        const int rowbase = unit * WROWS;
#pragma unroll
        for (int i = 0; i < 4; i++) {
            const int idx = i * 32 + lane;
            const int r = idx >> 2;          // 0..31
            const int c = idx & 3;           // float4 within 64B row-chunk
            const int grow = rowbase + r;
            const int ok = (grow < n);
            const float* src = x1 + (size_t)(ok ? grow : 0) * D + ch * CH + c * 4;
            cp_async16(base + (uint32_t)(r * ROWSTRIDE + c * 16), src, ok ? 16 : 0);
        }
    };

    const int gw0 = blockIdx.x * WARPS + wid;

    // prologue: chunk 0 of first unit in flight before header load
    if (gw0 < nunits) { issue(gw0, 0, 0); }
    cp_commit();

    // header: A, c, U (single block barrier in whole kernel)
    {
        const unsigned long long* gAu = (const unsigned long long*)gAp;
#pragma unroll
        for (int i = 0; i < 8; i++) sA[tid + i * TPB] = gAu[tid + i * TPB];
        if (tid < K) { sC[tid] = gC[tid]; sU[tid] = U[tid]; }
    }
    __syncthreads();

    for (int u = gw0; u < nunits; u += nw) {
        unsigned long long acc[4][4];    // [row rr][k j]; k = h2*4 + j
#pragma unroll
        for (int rr = 0; rr < 4; rr++)
#pragma unroll
            for (int j = 0; j < 4; j++) acc[rr][j] = 0ull;

        // one chunk: issue lookahead (static parity), wait, compute from buf
        auto chunk = [&](int ch, int buf) {
            if (ch < NCH - 1) {
                issue(u, ch + 1, buf ^ 1);
            } else {
                const int u2 = u + nw;
                if (u2 < nunits) issue(u2, 0, buf ^ 1);
            }
            cp_commit();
            cp_wait1();
            __syncwarp();

            const uint32_t wb = wstage_u32 + (uint32_t)buf * STAGE_BYTES + xoff;
            const uint32_t ab = sA_u32 + (uint32_t)(ch * 8) * 128;
#pragma unroll
            for (int q = 0; q < 4; q++) {          // 16B quads of the 64B chunk-row
                ulonglong2 xq[4];
#pragma unroll
                for (int rr = 0; rr < 4; rr++)
                    xq[rr] = lds128(wb + (uint32_t)(rr * 8 * ROWSTRIDE + q * 16));
#pragma unroll
                for (int e = 0; e < 2; e++) {      // col-pair within quad
                    const uint32_t acp = ab + (uint32_t)(q * 2 + e) * 128;
                    const ulonglong2 a01 = lds128(acp);        // k = h2*4, +1
                    const ulonglong2 a23 = lds128(acp + 16);   // k = h2*4+2, +3
#pragma unroll
                    for (int rr = 0; rr < 4; rr++) {
                        const unsigned long long xv = e ? xq[rr].y : xq[rr].x;
                        ffma2(acc[rr][0], xv, a01.x);
                        ffma2(acc[rr][1], xv, a01.y);
                        ffma2(acc[rr][2], xv, a23.x);
                        ffma2(acc[rr][3], xv, a23.y);
                    }
                }
            }
            __syncwarp();      // WAR: all lanes done with buf before it is re-issued
        };

#pragma unroll 1
        for (int ch2 = 0; ch2 < NCH; ch2 += 2) {   // manual 2x: static buffer parity
            chunk(ch2, 0);
            chunk(ch2 + 1, 1);
        }

        // epilogue: per-row partial over lane's 4 k, reduce across the 4-lane k-group
#pragma unroll
        for (int rr = 0; rr < 4; rr++) {
            float part = 0.f;
#pragma unroll
            for (int j = 0; j < 4; j++) {
                float lo, hi;
                unpack2(lo, hi, acc[rr][j]);
                const int k = h2 * 4 + j;
                const float s = lo + hi + sC[k];
                part = fmaf(fmaxf(s, 0.f), sU[k], part);
            }
            part += __shfl_xor_sync(0xffffffffu, part, 1);
            part += __shfl_xor_sync(0xffffffffu, part, 2);
            const int row = u * WROWS + rr * 8 + p2;
            if (h2 == 0 && row < n) out[row] = part;
        }
    }
    asm volatile("cp.async.wait_all;\n" ::: "memory");
}

// ---------------- launch ----------------
extern "C" void kernel_launch(void* const* d_in, const int* in_sizes, int n_in,
                              void* d_out, int out_size) {
    const float* x1 = nullptr; const float* x2 = nullptr; const float* V = nullptr;
    const float* W = nullptr;  const float* b = nullptr;  const float* U = nullptr;
    int n16 = 0;
    for (int i = 0; i < n_in; i++) {
        const int s = in_sizes[i];
        const float* p = (const float*)d_in[i];
        if (s == 128) x2 = p;
        else if (s == 4096) V = p;
        else if (s == 262144) W = p;
        else if (s == 16) { if (n16++ == 0) b = p; else U = p; }
        else x1 = p;
    }
    int n = 0;
    for (int i = 0; i < n_in; i++) if ((const float*)d_in[i] == x1) n = in_sizes[i] / D;

    float* out = (float*)d_out;

    ntn_prep<<<129, TPB>>>(x2, V, W, b);

    const int nunits = (n + WROWS - 1) / WROWS;
    int blocks = (nunits + WARPS - 1) / WARPS;
    if (blocks > NBLK) blocks = NBLK;
    const int nw = blocks * WARPS;
    cudaFuncSetAttribute(ntn_main, cudaFuncAttributeMaxDynamicSharedMemorySize, SMEM_TOTAL);
    ntn_main<<<blocks, TPB, SMEM_TOTAL>>>(x1, U, out, n, nunits, nw);
}

// round 14
// speedup vs baseline: 2.2610x; 1.1149x over previous
#include <cuda_runtime.h>
#include <stdint.h>

#define D 128
#define K 16
#define TPB 128
#define WARPS 4
#define WROWS 32                // rows per warp unit
#define CH 32                   // columns per chunk (128B/row)
#define NCH 4                   // chunks per unit
#define ROWSTRIDE 144           // 128B data + 16B pad (LDS.32 frag loads conflict-free)
#define STAGE_BYTES (WROWS * ROWSTRIDE)      // 4608
#define WARP_STAGING (2 * STAGE_BYTES)       // 9216
#define ASTRIDE 132             // floats per A row in smem (132*4=528B; banks 4n+c distinct)
#define SM_AH 0                 // A_hi: 16*528 = 8448
#define SM_AL 8448              // A_lo: 8448
#define SM_CU 16896             // c (16f) + U (16f)
#define SMEM_HDR 17024
#define SMEM_TOTAL (SMEM_HDR + WARPS * WARP_STAGING)   // 53888 -> 4 CTAs/SM
#define NBLK 592                // persistent: 148 SMs x 4 CTAs

__device__ float gA[K * D];     // A row-major [k][d] (full fp32)
__device__ float gAlo[K * D];   // A - trunc_tf32(A)
__device__ float gC[K];

// ---------------- helpers ----------------
__device__ __forceinline__ void cp_async16(uint32_t dst, const void* src, int src_bytes) {
    asm volatile("cp.async.cg.shared.global [%0], [%1], 16, %2;\n"
                 :: "r"(dst), "l"(src), "r"(src_bytes));
}
__device__ __forceinline__ void cp_commit() {
    asm volatile("cp.async.commit_group;\n" ::: "memory");
}
__device__ __forceinline__ void cp_wait1() {
    asm volatile("cp.async.wait_group 1;\n" ::: "memory");
}
__device__ __forceinline__ uint32_t lds32(uint32_t addr) {
    uint32_t v;
    asm volatile("ld.shared.b32 %0, [%1];" : "=r"(v) : "r"(addr));
    return v;
}
// D += A(16x8 tf32, row) @ B(8x8 tf32, col)
__device__ __forceinline__ void mma_tf32(float* c,
                                         uint32_t a0, uint32_t a1, uint32_t a2, uint32_t a3,
                                         uint32_t b0, uint32_t b1) {
    asm volatile(
        "mma.sync.aligned.m16n8k8.row.col.f32.tf32.tf32.f32 "
        "{%0,%1,%2,%3}, {%4,%5,%6,%7}, {%8,%9}, {%0,%1,%2,%3};"
        : "+f"(c[0]), "+f"(c[1]), "+f"(c[2]), "+f"(c[3])
        : "r"(a0), "r"(a1), "r"(a2), "r"(a3), "r"(b0), "r"(b1));
}

// ---------------- merged prep (single launch) ----------------
__global__ void ntn_prep(const float* __restrict__ x2,
                         const float* __restrict__ V,
                         const float* __restrict__ W,
                         const float* __restrict__ b) {
    const int lane = threadIdx.x & 31;
    const int wid = threadIdx.x >> 5;
    const float4 x4 = ((const float4*)x2)[lane];

    if (blockIdx.x < 128) {
        const int gw = blockIdx.x * 4 + wid;        // 0..511, rows 4gw..4gw+3
        float4 w4[4];
#pragma unroll
        for (int rr = 0; rr < 4; rr++)
            w4[rr] = ((const float4*)(W + (size_t)(gw * 4 + rr) * D))[lane];
        float dots[4];
#pragma unroll
        for (int rr = 0; rr < 4; rr++)
            dots[rr] = w4[rr].x * x4.x + w4[rr].y * x4.y + w4[rr].z * x4.z + w4[rr].w * x4.w;
#pragma unroll
        for (int s = 16; s > 0; s >>= 1) {
#pragma unroll
            for (int rr = 0; rr < 4; rr++)
                dots[rr] += __shfl_xor_sync(0xffffffffu, dots[rr], s);
        }
        if (lane == 0) {
#pragma unroll
            for (int rr = 0; rr < 4; rr++) {
                const int row = gw * 4 + rr;        // = k*128 + d
                const int k = row >> 7;
                const float a = V[(size_t)k * 2 * D + (row & (D - 1))] + dots[rr];
                const float hi = __uint_as_float(__float_as_uint(a) & 0xFFFFE000u);
                gA[row] = a;                        // full precision (hi used via mask on load)
                gAlo[row] = a - hi;
            }
        }
    } else {
#pragma unroll
        for (int kk = 0; kk < 4; kk++) {
            const int k = wid * 4 + kk;
            const float4 v4 = ((const float4*)(V + (size_t)k * 2 * D + D))[lane];
            float dot = v4.x * x4.x + v4.y * x4.y + v4.z * x4.z + v4.w * x4.w;
#pragma unroll
            for (int s = 16; s > 0; s >>= 1)
                dot += __shfl_xor_sync(0xffffffffu, dot, s);
            if (lane == 0) gC[k] = dot + b[k];
        }
    }
}

// ---------------- main: mma.sync tf32 with split compensation, per-warp cp.async pipeline ----------------
__global__ __launch_bounds__(TPB, 4)
void ntn_main(const float* __restrict__ x1,
              const float* __restrict__ U,
              float* __restrict__ out, int n, int nunits, int nw) {
    extern __shared__ __align__(16) char sm[];
    float* sC = (float*)(sm + SM_CU);
    float* sU = sC + K;

    const int tid = threadIdx.x;
    const int wid = tid >> 5;
    const int lane = tid & 31;
    const int lq = lane >> 2;        // fragment row group 0..7
    const int lr = lane & 3;         // fragment col group 0..3

    const uint32_t smb = (uint32_t)__cvta_generic_to_shared(sm);
    const uint32_t sAh_u = smb + SM_AH;
    const uint32_t sAl_u = smb + SM_AL;
    const uint32_t wstage = smb + SMEM_HDR + (uint32_t)wid * WARP_STAGING;

    // per-warp chunk issue: 32 rows x 32 cols (128B/row) -> 8 cp.async16 per lane
    auto issue = [&](int unit, int ch, int buf) {
        const uint32_t base = wstage + (uint32_t)buf * STAGE_BYTES;
        const int rowbase = unit * WROWS;
#pragma unroll
        for (int i = 0; i < 8; i++) {
            const int idx = i * 32 + lane;
            const int r = idx >> 3;          // 0..31
            const int c = idx & 7;           // float4 within 128B row-chunk
            const int grow = rowbase + r;
            const int ok = (grow < n);
            const float* src = x1 + (size_t)(ok ? grow : 0) * D + ch * CH + c * 4;
            cp_async16(base + (uint32_t)(r * ROWSTRIDE + c * 16), src, ok ? 16 : 0);
        }
    };

    const int gw0 = blockIdx.x * WARPS + wid;

    // prologue: chunk 0 of first unit in flight before header load
    if (gw0 < nunits) issue(gw0, 0, 0);
    cp_commit();

    // header: A_hi / A_lo into padded smem, c, U (single block barrier)
    for (int i = tid; i < K * D; i += TPB) {
        const int k = i >> 7, d = i & (D - 1);
        const float a = gA[i];
        ((float*)sm)[k * ASTRIDE + d] = __uint_as_float(__float_as_uint(a) & 0xFFFFE000u);
        ((float*)(sm + SM_AL))[k * ASTRIDE + d] = gAlo[i];
    }
    if (tid < K) { sC[tid] = gC[tid]; sU[tid] = U[tid]; }
    __syncthreads();

    for (int u = gw0; u < nunits; u += nw) {
        float acc[2][2][4];   // [m-tile][n-tile][frag]
#pragma unroll
        for (int m = 0; m < 2; m++)
#pragma unroll
            for (int t = 0; t < 2; t++)
#pragma unroll
                for (int j = 0; j < 4; j++) acc[m][t][j] = 0.f;

        auto chunk = [&](int ch, int buf) {
            // issue next chunk in stream (static parity)
            if (ch < NCH - 1) {
                issue(u, ch + 1, buf ^ 1);
            } else {
                const int u2 = u + nw;
                if (u2 < nunits) issue(u2, 0, buf ^ 1);
            }
            cp_commit();
            cp_wait1();
            __syncwarp();

            const uint32_t wb = wstage + (uint32_t)buf * STAGE_BYTES;
#pragma unroll
            for (int ks = 0; ks < 4; ks++) {
                const int kg = ch * CH + ks * 8;       // global k (D-dim) of this step
                // B fragments: B[k][n] = Amat[n][k]; b0 at k=lr, n=lq; b1 at k=lr+4
                uint32_t bh[2][2], bl[2][2];
#pragma unroll
                for (int t = 0; t < 2; t++) {
                    const uint32_t ab = (uint32_t)(((t * 8 + lq) * ASTRIDE + kg + lr) * 4);
                    bh[t][0] = lds32(sAh_u + ab);
                    bh[t][1] = lds32(sAh_u + ab + 16);
                    bl[t][0] = lds32(sAl_u + ab);
                    bl[t][1] = lds32(sAl_u + ab + 16);
                }
#pragma unroll
                for (int m = 0; m < 2; m++) {
                    // A(x) fragment: a0 (row lq, col lr), a1 (row+8), a2 (col+4), a3 (both)
                    const uint32_t xb = wb + (uint32_t)((m * 16 + lq) * ROWSTRIDE + (ks * 8 + lr) * 4);
                    const uint32_t x0 = lds32(xb);
                    const uint32_t x1r = lds32(xb + 8 * ROWSTRIDE);
                    const uint32_t x2r = lds32(xb + 16);
                    const uint32_t x3r = lds32(xb + 8 * ROWSTRIDE + 16);
                    const uint32_t h0 = x0 & 0xFFFFE000u, h1 = x1r & 0xFFFFE000u;
                    const uint32_t h2 = x2r & 0xFFFFE000u, h3 = x3r & 0xFFFFE000u;
                    const uint32_t l0 = __float_as_uint(__uint_as_float(x0) - __uint_as_float(h0));
                    const uint32_t l1 = __float_as_uint(__uint_as_float(x1r) - __uint_as_float(h1));
                    const uint32_t l2 = __float_as_uint(__uint_as_float(x2r) - __uint_as_float(h2));
                    const uint32_t l3 = __float_as_uint(__uint_as_float(x3r) - __uint_as_float(h3));
#pragma unroll
                    for (int t = 0; t < 2; t++) {
                        mma_tf32(acc[m][t], h0, h1, h2, h3, bh[t][0], bh[t][1]);  // xh @ Ah
                        mma_tf32(acc[m][t], l0, l1, l2, l3, bh[t][0], bh[t][1]);  // xl @ Ah
                        mma_tf32(acc[m][t], h0, h1, h2, h3, bl[t][0], bl[t][1]);  // xh @ Al
                    }
                }
            }
            __syncwarp();   // WAR before buf re-issue
        };

#pragma unroll 1
        for (int ch2 = 0; ch2 < NCH; ch2 += 2) {
            chunk(ch2, 0);
            chunk(ch2 + 1, 1);
        }

        // epilogue: thread holds D[row][k] for rows {m*16+lq, +8}, k = t*8 + 2*lr + {0,1}
#pragma unroll
        for (int m = 0; m < 2; m++) {
#pragma unroll
            for (int hh = 0; hh < 2; hh++) {
                float part = 0.f;
#pragma unroll
                for (int t = 0; t < 2; t++) {
#pragma unroll
                    for (int e = 0; e < 2; e++) {
                        const int k = t * 8 + 2 * lr + e;
                        const float v = acc[m][t][hh * 2 + e] + sC[k];
                        part = fmaf(fmaxf(v, 0.f), sU[k], part);
                    }
                }
                part += __shfl_xor_sync(0xffffffffu, part, 1);
                part += __shfl_xor_sync(0xffffffffu, part, 2);
                const int row = u * WROWS + m * 16 + hh * 8 + lq;
                if (lr == 0 && row < n) out[row] = part;
            }
        }
    }
    asm volatile("cp.async.wait_all;\n" ::: "memory");
}

// ---------------- launch ----------------
extern "C" void kernel_launch(void* const* d_in, const int* in_sizes, int n_in,
                              void* d_out, int out_size) {
    const float* x1 = nullptr; const float* x2 = nullptr; const float* V = nullptr;
    const float* W = nullptr;  const float* b = nullptr;  const float* U = nullptr;
    int n16 = 0;
    for (int i = 0; i < n_in; i++) {
        const int s = in_sizes[i];
        const float* p = (const float*)d_in[i];
        if (s == 128) x2 = p;
        else if (s == 4096) V = p;
        else if (s == 262144) W = p;
        else if (s == 16) { if (n16++ == 0) b = p; else U = p; }
        else x1 = p;
    }
    int n = 0;
    for (int i = 0; i < n_in; i++) if ((const float*)d_in[i] == x1) n = in_sizes[i] / D;

    float* out = (float*)d_out;

    ntn_prep<<<129, TPB>>>(x2, V, W, b);

    const int nunits = (n + WROWS - 1) / WROWS;
    int blocks = (nunits + WARPS - 1) / WARPS;
    if (blocks > NBLK) blocks = NBLK;
    const int nw = blocks * WARPS;
    cudaFuncSetAttribute(ntn_main, cudaFuncAttributeMaxDynamicSharedMemorySize, SMEM_TOTAL);
    ntn_main<<<blocks, TPB, SMEM_TOTAL>>>(x1, U, out, n, nunits, nw);
}

// round 15
// speedup vs baseline: 2.3393x; 1.0346x over previous
#include <cuda_runtime.h>
#include <stdint.h>

#define D 128
#define K 16
#define TPB 128
#define WARPS 4
#define WROWS 32                // rows per warp unit
#define CH 32                   // columns per chunk (128B/row)
#define NCH 4                   // chunks per unit
#define ROWSTRIDE 144           // 128B data + 16B pad (LDS.32 frag loads conflict-free)
#define STAGE_BYTES (WROWS * ROWSTRIDE)      // 4608
#define WARP_STAGING (2 * STAGE_BYTES)       // 9216
#define ASTRIDE 132             // floats per A row in smem (bank 4n+c, conflict-free)
#define SM_AH 0                 // A_hi: 16*528 = 8448
#define SM_CU 8448              // c (16f) + U (16f)
#define SMEM_HDR 8576
#define SMEM_TOTAL (SMEM_HDR + WARPS * WARP_STAGING)   // 45440 -> 5 CTAs/SM
#define NBLK 740                // persistent: 148 SMs x 5 CTAs

__device__ float gA[K * D];     // A row-major [k][d] (full fp32)
__device__ float gC[K];

// ---------------- helpers ----------------
__device__ __forceinline__ void cp_async16(uint32_t dst, const void* src, int src_bytes) {
    asm volatile("cp.async.cg.shared.global [%0], [%1], 16, %2;\n"
                 :: "r"(dst), "l"(src), "r"(src_bytes));
}
__device__ __forceinline__ void cp_commit() {
    asm volatile("cp.async.commit_group;\n" ::: "memory");
}
__device__ __forceinline__ void cp_wait1() {
    asm volatile("cp.async.wait_group 1;\n" ::: "memory");
}
__device__ __forceinline__ uint32_t lds32(uint32_t addr) {
    uint32_t v;
    asm volatile("ld.shared.b32 %0, [%1];" : "=r"(v) : "r"(addr));
    return v;
}
// D += A(16x8 tf32, row) @ B(8x8 tf32, col)
__device__ __forceinline__ void mma_tf32(float* c,
                                         uint32_t a0, uint32_t a1, uint32_t a2, uint32_t a3,
                                         uint32_t b0, uint32_t b1) {
    asm volatile(
        "mma.sync.aligned.m16n8k8.row.col.f32.tf32.tf32.f32 "
        "{%0,%1,%2,%3}, {%4,%5,%6,%7}, {%8,%9}, {%0,%1,%2,%3};"
        : "+f"(c[0]), "+f"(c[1]), "+f"(c[2]), "+f"(c[3])
        : "r"(a0), "r"(a1), "r"(a2), "r"(a3), "r"(b0), "r"(b1));
}

// ---------------- merged prep (single launch) ----------------
__global__ void ntn_prep(const float* __restrict__ x2,
                         const float* __restrict__ V,
                         const float* __restrict__ W,
                         const float* __restrict__ b) {
    const int lane = threadIdx.x & 31;
    const int wid = threadIdx.x >> 5;
    const float4 x4 = ((const float4*)x2)[lane];

    if (blockIdx.x < 128) {
        const int gw = blockIdx.x * 4 + wid;        // 0..511, rows 4gw..4gw+3
        float4 w4[4];
#pragma unroll
        for (int rr = 0; rr < 4; rr++)
            w4[rr] = ((const float4*)(W + (size_t)(gw * 4 + rr) * D))[lane];
        float dots[4];
#pragma unroll
        for (int rr = 0; rr < 4; rr++)
            dots[rr] = w4[rr].x * x4.x + w4[rr].y * x4.y + w4[rr].z * x4.z + w4[rr].w * x4.w;
#pragma unroll
        for (int s = 16; s > 0; s >>= 1) {
#pragma unroll
            for (int rr = 0; rr < 4; rr++)
                dots[rr] += __shfl_xor_sync(0xffffffffu, dots[rr], s);
        }
        if (lane == 0) {
#pragma unroll
            for (int rr = 0; rr < 4; rr++) {
                const int row = gw * 4 + rr;        // = k*128 + d
                const int k = row >> 7;
                gA[row] = V[(size_t)k * 2 * D + (row & (D - 1))] + dots[rr];
            }
        }
    } else {
#pragma unroll
        for (int kk = 0; kk < 4; kk++) {
            const int k = wid * 4 + kk;
            const float4 v4 = ((const float4*)(V + (size_t)k * 2 * D + D))[lane];
            float dot = v4.x * x4.x + v4.y * x4.y + v4.z * x4.z + v4.w * x4.w;
#pragma unroll
            for (int s = 16; s > 0; s >>= 1)
                dot += __shfl_xor_sync(0xffffffffu, dot, s);
            if (lane == 0) gC[k] = dot + b[k];
        }
    }
}

// ---------------- main: mma.sync tf32, x split-compensated (xh@Ah + xl@Ah) ----------------
__global__ __launch_bounds__(TPB, 5)
void ntn_main(const float* __restrict__ x1,
              const float* __restrict__ U,
              float* __restrict__ out, int n, int nunits, int nw) {
    extern __shared__ __align__(16) char sm[];
    float* sC = (float*)(sm + SM_CU);
    float* sU = sC + K;

    const int tid = threadIdx.x;
    const int wid = tid >> 5;
    const int lane = tid & 31;
    const int lq = lane >> 2;        // fragment row group 0..7
    const int lr = lane & 3;         // fragment col group 0..3

    const uint32_t smb = (uint32_t)__cvta_generic_to_shared(sm);
    const uint32_t sAh_u = smb + SM_AH;
    const uint32_t wstage = smb + SMEM_HDR + (uint32_t)wid * WARP_STAGING;

    // per-warp chunk issue: 32 rows x 32 cols (128B/row) -> 8 cp.async16 per lane
    auto issue = [&](int unit, int ch, int buf) {
        const uint32_t base = wstage + (uint32_t)buf * STAGE_BYTES;
        const int rowbase = unit * WROWS;
#pragma unroll
        for (int i = 0; i < 8; i++) {
            const int idx = i * 32 + lane;
            const int r = idx >> 3;          // 0..31
            const int c = idx & 7;           // float4 within 128B row-chunk
            const int grow = rowbase + r;
            const int ok = (grow < n);
            const float* src = x1 + (size_t)(ok ? grow : 0) * D + ch * CH + c * 4;
            cp_async16(base + (uint32_t)(r * ROWSTRIDE + c * 16), src, ok ? 16 : 0);
        }
    };

    const int gw0 = blockIdx.x * WARPS + wid;

    // prologue: chunk 0 of first unit in flight before header load
    if (gw0 < nunits) issue(gw0, 0, 0);
    cp_commit();

    // header: A_hi (tf32-truncated) into padded smem, c, U (single block barrier)
    for (int i = tid; i < K * D; i += TPB) {
        const int k = i >> 7, d = i & (D - 1);
        ((float*)sm)[k * ASTRIDE + d] = __uint_as_float(__float_as_uint(gA[i]) & 0xFFFFE000u);
    }
    if (tid < K) { sC[tid] = gC[tid]; sU[tid] = U[tid]; }
    __syncthreads();

    for (int u = gw0; u < nunits; u += nw) {
        float acc[2][2][4];   // [m-tile][n-tile][frag]
#pragma unroll
        for (int m = 0; m < 2; m++)
#pragma unroll
            for (int t = 0; t < 2; t++)
#pragma unroll
                for (int j = 0; j < 4; j++) acc[m][t][j] = 0.f;

        auto chunk = [&](int ch, int buf) {
            // issue next chunk in stream (static parity)
            if (ch < NCH - 1) {
                issue(u, ch + 1, buf ^ 1);
            } else {
                const int u2 = u + nw;
                if (u2 < nunits) issue(u2, 0, buf ^ 1);
            }
            cp_commit();
            cp_wait1();
            __syncwarp();

            const uint32_t wb = wstage + (uint32_t)buf * STAGE_BYTES;
#pragma unroll
            for (int ks = 0; ks < 4; ks++) {
                const int kg = ch * CH + ks * 8;       // global k (D-dim) of this step
                // B fragments from A_hi: b0 at k=lr, n=lq(+t*8); b1 at k=lr+4
                uint32_t bh[2][2];
#pragma unroll
                for (int t = 0; t < 2; t++) {
                    const uint32_t ab = (uint32_t)(((t * 8 + lq) * ASTRIDE + kg + lr) * 4);
                    bh[t][0] = lds32(sAh_u + ab);
                    bh[t][1] = lds32(sAh_u + ab + 16);
                }
#pragma unroll
                for (int m = 0; m < 2; m++) {
                    // x fragment: rows {m*16+lq, +8}, cols {lr, lr+4} of this 8-k step
                    const uint32_t xb = wb + (uint32_t)((m * 16 + lq) * ROWSTRIDE + (ks * 8 + lr) * 4);
                    const uint32_t x0 = lds32(xb);
                    const uint32_t x1r = lds32(xb + 8 * ROWSTRIDE);
                    const uint32_t x2r = lds32(xb + 16);
                    const uint32_t x3r = lds32(xb + 8 * ROWSTRIDE + 16);
                    const uint32_t h0 = x0 & 0xFFFFE000u, h1 = x1r & 0xFFFFE000u;
                    const uint32_t h2 = x2r & 0xFFFFE000u, h3 = x3r & 0xFFFFE000u;
                    const uint32_t l0 = __float_as_uint(__uint_as_float(x0) - __uint_as_float(h0));
                    const uint32_t l1 = __float_as_uint(__uint_as_float(x1r) - __uint_as_float(h1));
                    const uint32_t l2 = __float_as_uint(__uint_as_float(x2r) - __uint_as_float(h2));
                    const uint32_t l3 = __float_as_uint(__uint_as_float(x3r) - __uint_as_float(h3));
#pragma unroll
                    for (int t = 0; t < 2; t++) {
                        mma_tf32(acc[m][t], h0, h1, h2, h3, bh[t][0], bh[t][1]);  // xh @ Ah
                        mma_tf32(acc[m][t], l0, l1, l2, l3, bh[t][0], bh[t][1]);  // xl @ Ah
                    }
                }
            }
            __syncwarp();   // WAR before buf re-issue
        };

#pragma unroll 1
        for (int ch2 = 0; ch2 < NCH; ch2 += 2) {
            chunk(ch2, 0);
            chunk(ch2 + 1, 1);
        }

        // epilogue: thread holds D[row][k] for rows {m*16+lq, +8}, k = t*8 + 2*lr + {0,1}
#pragma unroll
        for (int m = 0; m < 2; m++) {
#pragma unroll
            for (int hh = 0; hh < 2; hh++) {
                float part = 0.f;
#pragma unroll
                for (int t = 0; t < 2; t++) {
#pragma unroll
                    for (int e = 0; e < 2; e++) {
                        const int k = t * 8 + 2 * lr + e;
                        const float v = acc[m][t][hh * 2 + e] + sC[k];
                        part = fmaf(fmaxf(v, 0.f), sU[k], part);
                    }
                }
                part += __shfl_xor_sync(0xffffffffu, part, 1);
                part += __shfl_xor_sync(0xffffffffu, part, 2);
                const int row = u * WROWS + m * 16 + hh * 8 + lq;
                if (lr == 0 && row < n) out[row] = part;
            }
        }
    }
    asm volatile("cp.async.wait_all;\n" ::: "memory");
}

// ---------------- launch ----------------
extern "C" void kernel_launch(void* const* d_in, const int* in_sizes, int n_in,
                              void* d_out, int out_size) {
    const float* x1 = nullptr; const float* x2 = nullptr; const float* V = nullptr;
    const float* W = nullptr;  const float* b = nullptr;  const float* U = nullptr;
    int n16 = 0;
    for (int i = 0; i < n_in; i++) {
        const int s = in_sizes[i];
        const float* p = (const float*)d_in[i];
        if (s == 128) x2 = p;
        else if (s == 4096) V = p;
        else if (s == 262144) W = p;
        else if (s == 16) { if (n16++ == 0) b = p; else U = p; }
        else x1 = p;
    }
    int n = 0;
    for (int i = 0; i < n_in; i++) if ((const float*)d_in[i] == x1) n = in_sizes[i] / D;

    float* out = (float*)d_out;

    ntn_prep<<<129, TPB>>>(x2, V, W, b);

    const int nunits = (n + WROWS - 1) / WROWS;
    int blocks = (nunits + WARPS - 1) / WARPS;
    if (blocks > NBLK) blocks = NBLK;
    const int nw = blocks * WARPS;
    cudaFuncSetAttribute(ntn_main, cudaFuncAttributeMaxDynamicSharedMemorySize, SMEM_TOTAL);
    ntn_main<<<blocks, TPB, SMEM_TOTAL>>>(x1, U, out, n, nunits, nw);
}

// round 16
// speedup vs baseline: 2.3447x; 1.0023x over previous
#include <cuda_runtime.h>
#include <stdint.h>

#define D 128
#define K 16
#define TPB 128
#define WARPS 4
#define WROWS 16                // rows per warp unit (small units -> low quantization tax)
#define CH 64                   // columns per chunk (256B/row)
#define NCH 2                   // chunks per unit
#define ROWSTRIDE 272           // 256B data + 16B pad (LDS.32 frag loads conflict-free)
#define STAGE_BYTES (WROWS * ROWSTRIDE)      // 4352
#define WARP_STAGING (2 * STAGE_BYTES)       // 8704
#define ASTRIDE 132             // floats per A row in smem (bank 4n+c, conflict-free)
#define SM_AH 0                 // A_hi: 16*528 = 8448
#define SM_CU 8448              // c (16f) + U (16f)
#define SMEM_HDR 8576
#define SMEM_TOTAL (SMEM_HDR + WARPS * WARP_STAGING)   // 43392 -> 5 CTAs/SM
#define NBLK 740                // persistent: 148 SMs x 5 CTAs

__device__ float gA[K * D];     // A row-major [k][d] (full fp32)
__device__ float gC[K];

// ---------------- helpers ----------------
__device__ __forceinline__ void cp_async16(uint32_t dst, const void* src, int src_bytes) {
    asm volatile("cp.async.cg.shared.global [%0], [%1], 16, %2;\n"
                 :: "r"(dst), "l"(src), "r"(src_bytes));
}
__device__ __forceinline__ void cp_commit() {
    asm volatile("cp.async.commit_group;\n" ::: "memory");
}
__device__ __forceinline__ void cp_wait1() {
    asm volatile("cp.async.wait_group 1;\n" ::: "memory");
}
__device__ __forceinline__ uint32_t lds32(uint32_t addr) {
    uint32_t v;
    asm volatile("ld.shared.b32 %0, [%1];" : "=r"(v) : "r"(addr));
    return v;
}
// D += A(16x8 tf32, row) @ B(8x8 tf32, col)
__device__ __forceinline__ void mma_tf32(float* c,
                                         uint32_t a0, uint32_t a1, uint32_t a2, uint32_t a3,
                                         uint32_t b0, uint32_t b1) {
    asm volatile(
        "mma.sync.aligned.m16n8k8.row.col.f32.tf32.tf32.f32 "
        "{%0,%1,%2,%3}, {%4,%5,%6,%7}, {%8,%9}, {%0,%1,%2,%3};"
        : "+f"(c[0]), "+f"(c[1]), "+f"(c[2]), "+f"(c[3])
        : "r"(a0), "r"(a1), "r"(a2), "r"(a3), "r"(b0), "r"(b1));
}

// ---------------- merged prep (single launch) ----------------
__global__ void ntn_prep(const float* __restrict__ x2,
                         const float* __restrict__ V,
                         const float* __restrict__ W,
                         const float* __restrict__ b) {
    const int lane = threadIdx.x & 31;
    const int wid = threadIdx.x >> 5;
    const float4 x4 = ((const float4*)x2)[lane];

    if (blockIdx.x < 128) {
        const int gw = blockIdx.x * 4 + wid;        // 0..511, rows 4gw..4gw+3
        float4 w4[4];
#pragma unroll
        for (int rr = 0; rr < 4; rr++)
            w4[rr] = ((const float4*)(W + (size_t)(gw * 4 + rr) * D))[lane];
        float dots[4];
#pragma unroll
        for (int rr = 0; rr < 4; rr++)
            dots[rr] = w4[rr].x * x4.x + w4[rr].y * x4.y + w4[rr].z * x4.z + w4[rr].w * x4.w;
#pragma unroll
        for (int s = 16; s > 0; s >>= 1) {
#pragma unroll
            for (int rr = 0; rr < 4; rr++)
                dots[rr] += __shfl_xor_sync(0xffffffffu, dots[rr], s);
        }
        if (lane == 0) {
#pragma unroll
            for (int rr = 0; rr < 4; rr++) {
                const int row = gw * 4 + rr;        // = k*128 + d
                const int k = row >> 7;
                gA[row] = V[(size_t)k * 2 * D + (row & (D - 1))] + dots[rr];
            }
        }
    } else {
#pragma unroll
        for (int kk = 0; kk < 4; kk++) {
            const int k = wid * 4 + kk;
            const float4 v4 = ((const float4*)(V + (size_t)k * 2 * D + D))[lane];
            float dot = v4.x * x4.x + v4.y * x4.y + v4.z * x4.z + v4.w * x4.w;
#pragma unroll
            for (int s = 16; s > 0; s >>= 1)
                dot += __shfl_xor_sync(0xffffffffu, dot, s);
            if (lane == 0) gC[k] = dot + b[k];
        }
    }
}

// ---------------- main: mma.sync tf32 (xh@Ah + xl@Ah), 16-row units ----------------
__global__ __launch_bounds__(TPB, 5)
void ntn_main(const float* __restrict__ x1,
              const float* __restrict__ U,
              float* __restrict__ out, int n, int nunits, int nw) {
    extern __shared__ __align__(16) char sm[];
    float* sC = (float*)(sm + SM_CU);
    float* sU = sC + K;

    const int tid = threadIdx.x;
    const int wid = tid >> 5;
    const int lane = tid & 31;
    const int lq = lane >> 2;        // fragment row group 0..7
    const int lr = lane & 3;         // fragment col group 0..3

    const uint32_t smb = (uint32_t)__cvta_generic_to_shared(sm);
    const uint32_t sAh_u = smb + SM_AH;
    const uint32_t wstage = smb + SMEM_HDR + (uint32_t)wid * WARP_STAGING;

    // per-warp chunk issue: 16 rows x 64 cols (256B/row) -> 8 cp.async16 per lane
    auto issue = [&](int unit, int ch, int buf) {
        const uint32_t base = wstage + (uint32_t)buf * STAGE_BYTES;
        const int rowbase = unit * WROWS;
#pragma unroll
        for (int i = 0; i < 8; i++) {
            const int idx = i * 32 + lane;
            const int r = idx >> 4;          // 0..15
            const int c = idx & 15;          // float4 within 256B row-chunk
            const int grow = rowbase + r;
            const int ok = (grow < n);
            const float* src = x1 + (size_t)(ok ? grow : 0) * D + ch * CH + c * 4;
            cp_async16(base + (uint32_t)(r * ROWSTRIDE + c * 16), src, ok ? 16 : 0);
        }
    };

    const int gw0 = blockIdx.x * WARPS + wid;

    // prologue: chunk 0 of first unit in flight before header load
    if (gw0 < nunits) issue(gw0, 0, 0);
    cp_commit();

    // header: A_hi (RN-rounded tf32) into padded smem, c, U (single block barrier)
    for (int i = tid; i < K * D; i += TPB) {
        const int k = i >> 7, d = i & (D - 1);
        float h;
        asm("cvt.rna.tf32.f32 %0, %1;" : "=f"(h) : "f"(gA[i]));
        ((float*)sm)[k * ASTRIDE + d] = h;
    }
    if (tid < K) { sC[tid] = gC[tid]; sU[tid] = U[tid]; }
    __syncthreads();

    for (int u = gw0; u < nunits; u += nw) {
        float acc[2][4];   // [n-tile t][frag]
#pragma unroll
        for (int t = 0; t < 2; t++)
#pragma unroll
            for (int j = 0; j < 4; j++) acc[t][j] = 0.f;

        auto chunk = [&](int ch, int buf) {
            // issue next chunk in stream (static parity)
            if (ch < NCH - 1) {
                issue(u, ch + 1, buf ^ 1);
            } else {
                const int u2 = u + nw;
                if (u2 < nunits) issue(u2, 0, buf ^ 1);
            }
            cp_commit();
            cp_wait1();
            __syncwarp();

            const uint32_t wb = wstage + (uint32_t)buf * STAGE_BYTES;
#pragma unroll
            for (int ks = 0; ks < 8; ks++) {           // 8 k-steps of 8 within 64-col chunk
                const int kg = ch * CH + ks * 8;       // global k (D-dim) of this step
                // B fragments from A_hi: b0 at k=lr, n=lq(+t*8); b1 at k=lr+4
                uint32_t bh[2][2];
#pragma unroll
                for (int t = 0; t < 2; t++) {
                    const uint32_t ab = (uint32_t)(((t * 8 + lq) * ASTRIDE + kg + lr) * 4);
                    bh[t][0] = lds32(sAh_u + ab);
                    bh[t][1] = lds32(sAh_u + ab + 16);
                }
                // x fragment: rows {lq, lq+8}, cols {lr, lr+4} of this 8-k step
                const uint32_t xb = wb + (uint32_t)(lq * ROWSTRIDE + (ks * 8 + lr) * 4);
                const uint32_t x0 = lds32(xb);
                const uint32_t x1r = lds32(xb + 8 * ROWSTRIDE);
                const uint32_t x2r = lds32(xb + 16);
                const uint32_t x3r = lds32(xb + 8 * ROWSTRIDE + 16);
                const uint32_t h0 = x0 & 0xFFFFE000u, h1 = x1r & 0xFFFFE000u;
                const uint32_t h2 = x2r & 0xFFFFE000u, h3 = x3r & 0xFFFFE000u;
                const uint32_t l0 = __float_as_uint(__uint_as_float(x0) - __uint_as_float(h0));
                const uint32_t l1 = __float_as_uint(__uint_as_float(x1r) - __uint_as_float(h1));
                const uint32_t l2 = __float_as_uint(__uint_as_float(x2r) - __uint_as_float(h2));
                const uint32_t l3 = __float_as_uint(__uint_as_float(x3r) - __uint_as_float(h3));
#pragma unroll
                for (int t = 0; t < 2; t++) {
                    mma_tf32(acc[t], h0, h1, h2, h3, bh[t][0], bh[t][1]);  // xh @ Ah
                    mma_tf32(acc[t], l0, l1, l2, l3, bh[t][0], bh[t][1]);  // xl @ Ah
                }
            }
            __syncwarp();   // WAR before buf re-issue
        };

        chunk(0, 0);
        chunk(1, 1);

        // epilogue: thread holds D[row][k] for rows {lq, lq+8}, k = t*8 + 2*lr + {0,1}
#pragma unroll
        for (int hh = 0; hh < 2; hh++) {
            float part = 0.f;
#pragma unroll
            for (int t = 0; t < 2; t++) {
#pragma unroll
                for (int e = 0; e < 2; e++) {
                    const int k = t * 8 + 2 * lr + e;
                    const float v = acc[t][hh * 2 + e] + sC[k];
                    part = fmaf(fmaxf(v, 0.f), sU[k], part);
                }
            }
            part += __shfl_xor_sync(0xffffffffu, part, 1);
            part += __shfl_xor_sync(0xffffffffu, part, 2);
            const int row = u * WROWS + hh * 8 + lq;
            if (lr == 0 && row < n) out[row] = part;
        }
    }
    asm volatile("cp.async.wait_all;\n" ::: "memory");
}

// ---------------- launch ----------------
extern "C" void kernel_launch(void* const* d_in, const int* in_sizes, int n_in,
                              void* d_out, int out_size) {
    const float* x1 = nullptr; const float* x2 = nullptr; const float* V = nullptr;
    const float* W = nullptr;  const float* b = nullptr;  const float* U = nullptr;
    int n16 = 0;
    for (int i = 0; i < n_in; i++) {
        const int s = in_sizes[i];
        const float* p = (const float*)d_in[i];
        if (s == 128) x2 = p;
        else if (s == 4096) V = p;
        else if (s == 262144) W = p;
        else if (s == 16) { if (n16++ == 0) b = p; else U = p; }
        else x1 = p;
    }
    int n = 0;
    for (int i = 0; i < n_in; i++) if ((const float*)d_in[i] == x1) n = in_sizes[i] / D;

    float* out = (float*)d_out;

    ntn_prep<<<129, TPB>>>(x2, V, W, b);

    const int nunits = (n + WROWS - 1) / WROWS;
    int blocks = (nunits + WARPS - 1) / WARPS;
    if (blocks > NBLK) blocks = NBLK;
    const int nw = blocks * WARPS;
    cudaFuncSetAttribute(ntn_main, cudaFuncAttributeMaxDynamicSharedMemorySize, SMEM_TOTAL);
    ntn_main<<<blocks, TPB, SMEM_TOTAL>>>(x1, U, out, n, nunits, nw);
}